// round 6
// baseline (speedup 1.0000x reference)
#include <cuda_runtime.h>
#include <math.h>
#include <cstdint>

// ---------------------------------------------------------------------------
// NaN-interpolation, [1, 2M, 16] f32. element e -> column (e&15).
// reduce: TMA (cp.async.bulk) 4-stage pipeline into smem, 592 blocks (4/SM),
//         per-block partials (no global atomics)
// finalize: fold partials -> means
// fill: 1184 blocks, reverse-order streaming pass, MLP=4 (unchanged, known 6.8 TB/s)
// ---------------------------------------------------------------------------

#define COLS      16
#define RBLOCKS   (148 * 4)               // 592
#define FBLOCKS   (148 * 8)               // 1184
#define NTHREADS  256
#define FSTRIDE   (FBLOCKS * NTHREADS)    // 303104, multiple of 4

#define NSTAGES   4
#define STAGE_F4  512                     // float4s per stage (= 2 per thread)
#define STAGE_BYTES (STAGE_F4 * 16)       // 8192

__device__ float g_part_sum[RBLOCKS][COLS];
__device__ float g_part_cnt[RBLOCKS][COLS];
__device__ float g_mean[COLS];

// ---------------- PTX helpers ----------------
static __device__ __forceinline__ uint32_t smem_u32(const void* p) {
    return (uint32_t)__cvta_generic_to_shared(p);
}
static __device__ __forceinline__ void mbar_init(uint32_t a, uint32_t cnt) {
    asm volatile("mbarrier.init.shared.b64 [%0], %1;" :: "r"(a), "r"(cnt) : "memory");
}
static __device__ __forceinline__ void mbar_expect_tx(uint32_t a, uint32_t bytes) {
    asm volatile("mbarrier.arrive.expect_tx.shared.b64 _, [%0], %1;"
                 :: "r"(a), "r"(bytes) : "memory");
}
static __device__ __forceinline__ void mbar_arrive(uint32_t a) {
    asm volatile("mbarrier.arrive.shared.b64 _, [%0];" :: "r"(a) : "memory");
}
static __device__ __forceinline__ void mbar_wait_acq(uint32_t a, uint32_t ph) {
    asm volatile(
        "{\n\t.reg .pred P;\n\t"
        "WL_%=:\n\t"
        "mbarrier.try_wait.parity.acquire.cta.shared::cta.b64 P, [%0], %1, 0x989680;\n\t"
        "@P bra.uni WD_%=;\n\t"
        "bra.uni WL_%=;\n\t"
        "WD_%=:\n\t}"
        :: "r"(a), "r"(ph) : "memory");
}
static __device__ __forceinline__ void mbar_wait_rlx(uint32_t a, uint32_t ph) {
    asm volatile(
        "{\n\t.reg .pred P;\n\t"
        "WL_%=:\n\t"
        "mbarrier.try_wait.parity.relaxed.cta.shared::cta.b64 P, [%0], %1, 0x989680;\n\t"
        "@P bra.uni WD_%=;\n\t"
        "bra.uni WL_%=;\n\t"
        "WD_%=:\n\t}"
        :: "r"(a), "r"(ph) : "memory");
}
static __device__ __forceinline__ void bulk_g2s(uint32_t dst_smem, const void* src,
                                                uint32_t bytes, uint32_t mbar) {
    asm volatile(
        "cp.async.bulk.shared::cta.global.mbarrier::complete_tx::bytes [%0], [%1], %2, [%3];"
        :: "r"(dst_smem), "l"(src), "r"(bytes), "r"(mbar) : "memory");
}

// ---------------- accumulation ----------------
struct Acc { float s0, s1, s2, s3, c0, c1, c2, c3; };

static __device__ __forceinline__ void acc4(Acc& a, const float4& q) {
    bool v0 = (q.x == q.x), v1 = (q.y == q.y);
    bool v2 = (q.z == q.z), v3 = (q.w == q.w);
    a.s0 += v0 ? q.x : 0.0f;  a.c0 += v0 ? 1.0f : 0.0f;
    a.s1 += v1 ? q.y : 0.0f;  a.c1 += v1 ? 1.0f : 0.0f;
    a.s2 += v2 ? q.z : 0.0f;  a.c2 += v2 ? 1.0f : 0.0f;
    a.s3 += v3 ? q.w : 0.0f;  a.c3 += v3 ? 1.0f : 0.0f;
}

// ---------------- reduce: TMA pipeline ----------------
__global__ void __launch_bounds__(NTHREADS) interp_reduce_kernel(
    const float4* __restrict__ in, int n4)
{
    __shared__ __align__(16) float4 s_buf[NSTAGES][STAGE_F4];   // 32 KB
    __shared__ uint64_t s_full[NSTAGES];
    __shared__ uint64_t s_empty[NSTAGES];
    __shared__ float s_sum[COLS];
    __shared__ float s_cnt[COLS];

    const int t = threadIdx.x;
    const int b = blockIdx.x;

    uint32_t full_a[NSTAGES], empty_a[NSTAGES], buf_a[NSTAGES];
    #pragma unroll
    for (int s = 0; s < NSTAGES; s++) {
        full_a[s]  = smem_u32(&s_full[s]);
        empty_a[s] = smem_u32(&s_empty[s]);
        buf_a[s]   = smem_u32(&s_buf[s][0]);
    }

    if (t < COLS) { s_sum[t] = 0.0f; s_cnt[t] = 0.0f; }
    if (t == 0) {
        #pragma unroll
        for (int s = 0; s < NSTAGES; s++) {
            mbar_init(full_a[s], 1);          // completes via expect_tx + TMA bytes
            mbar_init(empty_a[s], NTHREADS);  // all consumers arrive
        }
    }
    __syncthreads();

    const int n_stages_tot = n4 / STAGE_F4;            // 15625 for n4 = 8M
    const int tail_base    = n_stages_tot * STAGE_F4;  // remainder elements (0 here)
    const int my_count     = (b < n_stages_tot) ? (n_stages_tot - 1 - b) / RBLOCKS + 1 : 0;

    // Prologue: producer issues up to NSTAGES stages ahead.
    if (t == 0) {
        int npro = my_count < NSTAGES ? my_count : NSTAGES;
        for (int i = 0; i < npro; i++) {
            int sg = b + i * RBLOCKS;
            mbar_expect_tx(full_a[i], STAGE_BYTES);
            bulk_g2s(buf_a[i], (const void*)(in + (size_t)sg * STAGE_F4),
                     STAGE_BYTES, full_a[i]);
        }
    }

    Acc a = {0.f, 0.f, 0.f, 0.f, 0.f, 0.f, 0.f, 0.f};

    for (int it = 0; it < my_count; it++) {
        const int slot = it & (NSTAGES - 1);
        const uint32_t par = (it >> 2) & 1;

        mbar_wait_acq(full_a[slot], par);
        float4 q0 = s_buf[slot][t];
        float4 q1 = s_buf[slot][t + NTHREADS];
        acc4(a, q0);
        acc4(a, q1);
        mbar_arrive(empty_a[slot]);

        if (t == 0 && it + NSTAGES < my_count) {
            // All 256 consumers of round (it>>2) must be done before refill.
            mbar_wait_rlx(empty_a[slot], par);
            int sg = b + (it + NSTAGES) * RBLOCKS;
            mbar_expect_tx(full_a[slot], STAGE_BYTES);
            bulk_g2s(buf_a[slot], (const void*)(in + (size_t)sg * STAGE_F4),
                     STAGE_BYTES, full_a[slot]);
        }
    }

    // Tail (n4 not divisible by STAGE_F4): block 0 handles the remainder directly.
    if (b == 0 && tail_base + t < n4) {
        float4 q = in[tail_base + t];
        acc4(a, q);
    }

    // Thread t accumulated columns 4*(t&3)..4*(t&3)+3 (stage bases are multiples of 4).
    const int g = t & 3;
    atomicAdd(&s_sum[4 * g + 0], a.s0);  atomicAdd(&s_cnt[4 * g + 0], a.c0);
    atomicAdd(&s_sum[4 * g + 1], a.s1);  atomicAdd(&s_cnt[4 * g + 1], a.c1);
    atomicAdd(&s_sum[4 * g + 2], a.s2);  atomicAdd(&s_cnt[4 * g + 2], a.c2);
    atomicAdd(&s_sum[4 * g + 3], a.s3);  atomicAdd(&s_cnt[4 * g + 3], a.c3);
    __syncthreads();

    if (t < COLS) {
        g_part_sum[b][t] = s_sum[t];
        g_part_cnt[b][t] = s_cnt[t];
    }
}

// ---------------- finalize ----------------
__global__ void __launch_bounds__(NTHREADS) interp_finalize_kernel() {
    __shared__ float sh_s[NTHREADS];
    __shared__ float sh_n[NTHREADS];
    const int t = threadIdx.x;
    const int c = t & 15;
    float S = 0.f, N = 0.f;
    for (int j = t >> 4; j < RBLOCKS; j += NTHREADS / 16) {
        S += g_part_sum[j][c];
        N += g_part_cnt[j][c];
    }
    sh_s[t] = S; sh_n[t] = N;
    __syncthreads();
    if (t < COLS) {
        float SS = 0.f, NN = 0.f;
        #pragma unroll
        for (int k = 0; k < NTHREADS / 16; k++) {
            SS += sh_s[k * 16 + t];
            NN += sh_n[k * 16 + t];
        }
        g_mean[t] = SS / fmaxf(NN, 1.0f);
    }
}

// ---------------- fill ----------------
static __device__ __forceinline__ float4 fill4(const float4& q,
                                               float m0, float m1,
                                               float m2, float m3) {
    float4 o;
    o.x = (q.x == q.x) ? q.x : m0;
    o.y = (q.y == q.y) ? q.y : m1;
    o.z = (q.z == q.z) ? q.z : m2;
    o.w = (q.w == q.w) ? q.w : m3;
    return o;
}

__global__ void __launch_bounds__(NTHREADS, 8) interp_fill_kernel(
    const float4* __restrict__ in, float4* __restrict__ out, int n4)
{
    const int t   = threadIdx.x;
    const int idx = blockIdx.x * NTHREADS + t;
    const int g   = idx & 3;

    const float m0 = g_mean[4 * g + 0];
    const float m1 = g_mean[4 * g + 1];
    const float m2 = g_mean[4 * g + 2];
    const float m3 = g_mean[4 * g + 3];

    if (idx >= n4) return;

    // Reverse grid-stride: start in the L2-resident tail left by the reduce.
    int v = idx + ((n4 - 1 - idx) / FSTRIDE) * FSTRIDE;

    for (; v - 3 * FSTRIDE >= 0; v -= 4 * FSTRIDE) {
        float4 q0 = __ldcs(&in[v]);
        float4 q1 = __ldcs(&in[v - FSTRIDE]);
        float4 q2 = __ldcs(&in[v - 2 * FSTRIDE]);
        float4 q3 = __ldcs(&in[v - 3 * FSTRIDE]);
        float4 o0 = fill4(q0, m0, m1, m2, m3);
        float4 o1 = fill4(q1, m0, m1, m2, m3);
        float4 o2 = fill4(q2, m0, m1, m2, m3);
        float4 o3 = fill4(q3, m0, m1, m2, m3);
        __stcs(&out[v],               o0);
        __stcs(&out[v - FSTRIDE],     o1);
        __stcs(&out[v - 2 * FSTRIDE], o2);
        __stcs(&out[v - 3 * FSTRIDE], o3);
    }
    for (; v >= 0; v -= FSTRIDE) {
        float4 q = __ldcs(&in[v]);
        __stcs(&out[v], fill4(q, m0, m1, m2, m3));
    }
}

extern "C" void kernel_launch(void* const* d_in, const int* in_sizes, int n_in,
                              void* d_out, int out_size)
{
    const float4* in  = (const float4*)d_in[0];
    float4*       out = (float4*)d_out;
    int n4 = in_sizes[0] / 4;   // 8,000,000 exact

    interp_reduce_kernel<<<RBLOCKS, NTHREADS>>>(in, n4);
    interp_finalize_kernel<<<1, NTHREADS>>>();
    interp_fill_kernel<<<FBLOCKS, NTHREADS>>>(in, out, n4);
}